// round 1
// baseline (speedup 1.0000x reference)
#include <cuda_runtime.h>

// Problem constants (fixed by reference): B=1, N=50000, H=8, D=16, E=800000
#define NNODES 50000
#define NEDGES 800000
#define HD     128          // H*D floats per node
// SCALE = sqrt(D) = 4  ->  multiply dot by 0.25

// Device-global scratch (no allocations allowed)
__device__ int g_count [NNODES];
__device__ int g_cursor[NNODES];
__device__ int g_offset[NNODES + 1];
__device__ int g_srclist[NEDGES];

// ---------------------------------------------------------------------------
__global__ void zero_kernel(int n) {
    int i = blockIdx.x * blockDim.x + threadIdx.x;
    if (i < n) { g_count[i] = 0; g_cursor[i] = 0; }
}

__global__ void hist_kernel(const int* __restrict__ ei, int E) {
    int e = blockIdx.x * blockDim.x + threadIdx.x;
    if (e < E) atomicAdd(&g_count[ei[E + e]], 1);   // dst row
}

// Single-block exclusive scan of g_count[0..n) -> g_offset[0..n], 1024 threads.
__global__ void scan_kernel(int n) {
    const int T = 1024;
    int tid = threadIdx.x;
    int chunk = (n + T - 1) / T;
    int beg = tid * chunk;
    int end = min(beg + chunk, n);

    int s = 0;
    for (int i = beg; i < end; i++) s += g_count[i];

    __shared__ int sh[T];
    sh[tid] = s;
    __syncthreads();
    // Hillis-Steele inclusive scan
    for (int off = 1; off < T; off <<= 1) {
        int t = (tid >= off) ? sh[tid - off] : 0;
        __syncthreads();
        sh[tid] += t;
        __syncthreads();
    }
    int run = sh[tid] - s;   // exclusive prefix of this thread's chunk
    for (int i = beg; i < end; i++) {
        g_offset[i] = run;
        run += g_count[i];
    }
    if (end == n) g_offset[n] = run;   // total (all qualifying threads write same value)
}

__global__ void scatter_kernel(const int* __restrict__ ei, int E) {
    int e = blockIdx.x * blockDim.x + threadIdx.x;
    if (e < E) {
        int dst = ei[E + e];
        int pos = g_offset[dst] + atomicAdd(&g_cursor[dst], 1);
        g_srclist[pos] = ei[e];      // src row
    }
}

// ---------------------------------------------------------------------------
// Main: one warp per destination node. Lane l owns floats [4l, 4l+4) of the
// 128-float node vector; head h = l>>2 (4 lanes per 16-dim head).
__global__ void attn_kernel(const float4* __restrict__ q,
                            const float4* __restrict__ k,
                            const float4* __restrict__ v,
                            float4* __restrict__ out,
                            int nnodes) {
    int gw   = (blockIdx.x * blockDim.x + threadIdx.x) >> 5;
    int lane = threadIdx.x & 31;
    if (gw >= nnodes) return;

    const int node = gw;
    const int beg = g_offset[node];
    const int end = g_offset[node + 1];

    const float4 q4 = q[node * 32 + lane];
    float4 acc = make_float4(0.f, 0.f, 0.f, 0.f);
    float  z   = 0.f;

    for (int i = beg; i < end; i++) {
        int src = __ldg(&g_srclist[i]);            // broadcast across warp
        float4 k4 = __ldg(&k[src * 32 + lane]);
        float d = q4.x * k4.x + q4.y * k4.y + q4.z * k4.z + q4.w * k4.w;
        // reduce across the 4-lane head group
        d += __shfl_xor_sync(0xffffffffu, d, 1);
        d += __shfl_xor_sync(0xffffffffu, d, 2);
        d *= 0.25f;                                 // 1/sqrt(16)
        d = fminf(fmaxf(d, -5.f), 5.f);
        float s = __expf(d);
        z += s;
        float4 v4 = __ldg(&v[src * 32 + lane]);
        acc.x += v4.x * s;
        acc.y += v4.y * s;
        acc.z += v4.z * s;
        acc.w += v4.w * s;
    }

    float inv = 1.f / (z + 1e-6f);
    float4 o;
    o.x = acc.x * inv; o.y = acc.y * inv; o.z = acc.z * inv; o.w = acc.w * inv;
    out[node * 32 + lane] = o;
}

// ---------------------------------------------------------------------------
extern "C" void kernel_launch(void* const* d_in, const int* in_sizes, int n_in,
                              void* d_out, int out_size) {
    const float* q  = (const float*)d_in[0];
    const float* k  = (const float*)d_in[1];
    const float* v  = (const float*)d_in[2];
    const int*   ei = (const int*)d_in[3];

    int E      = in_sizes[3] / 2;
    int nnodes = in_sizes[0] / HD;

    zero_kernel<<<(nnodes + 255) / 256, 256>>>(nnodes);
    hist_kernel<<<(E + 255) / 256, 256>>>(ei, E);
    scan_kernel<<<1, 1024>>>(nnodes);
    scatter_kernel<<<(E + 255) / 256, 256>>>(ei, E);

    int threads = 256;                       // 8 warps/block -> 8 nodes/block
    int blocks  = (nnodes * 32 + threads - 1) / threads;
    attn_kernel<<<blocks, threads>>>((const float4*)q, (const float4*)k,
                                     (const float4*)v, (float4*)d_out, nnodes);
}

// round 3
// speedup vs baseline: 1.0450x; 1.0450x over previous
#include <cuda_runtime.h>

// Problem constants (fixed by reference): B=1, N=50000, H=8, D=16, E=800000
#define NNODES 50000
#define NEDGES 800000
#define HD     128          // H*D floats per node

// Device-global scratch (no allocations allowed)
__device__ int g_count [NNODES];       // histogram, then reused as scatter cursor
__device__ int g_offset[NNODES + 1];
__device__ int g_srclist[NEDGES];

// ---------------------------------------------------------------------------
__global__ void hist_kernel(const int* __restrict__ ei, int E) {
    int t = blockIdx.x * blockDim.x + threadIdx.x;
    int e = t * 4;
    if (e + 4 <= E) {
        int4 d = *reinterpret_cast<const int4*>(&ei[E + e]);   // dst rows
        atomicAdd(&g_count[d.x], 1);
        atomicAdd(&g_count[d.y], 1);
        atomicAdd(&g_count[d.z], 1);
        atomicAdd(&g_count[d.w], 1);
    } else {
        for (; e < E; e++) atomicAdd(&g_count[ei[E + e]], 1);
    }
}

// Single-block exclusive scan of g_count[0..n) -> g_offset[0..n], 1024 threads.
__global__ void scan_kernel(int n) {
    const int T = 1024;
    int tid = threadIdx.x;
    int chunk = (n + T - 1) / T;
    int beg = tid * chunk;
    int end = min(beg + chunk, n);

    int s = 0;
    for (int i = beg; i < end; i++) s += g_count[i];

    __shared__ int sh[T];
    sh[tid] = s;
    __syncthreads();
    for (int off = 1; off < T; off <<= 1) {
        int t = (tid >= off) ? sh[tid - off] : 0;
        __syncthreads();
        sh[tid] += t;
        __syncthreads();
    }
    int run = sh[tid] - s;
    for (int i = beg; i < end; i++) {
        g_offset[i] = run;
        run += g_count[i];
    }
    if (end == n) g_offset[n] = run;
}

// Scatter: reuse g_count as a downward cursor (rank order within a bucket is
// irrelevant — attention sum is order-independent).
__global__ void scatter_kernel(const int* __restrict__ ei, int E) {
    int t = blockIdx.x * blockDim.x + threadIdx.x;
    int e = t * 4;
    if (e + 4 <= E) {
        int4 s = *reinterpret_cast<const int4*>(&ei[e]);       // src rows
        int4 d = *reinterpret_cast<const int4*>(&ei[E + e]);   // dst rows
        g_srclist[g_offset[d.x] + atomicSub(&g_count[d.x], 1) - 1] = s.x;
        g_srclist[g_offset[d.y] + atomicSub(&g_count[d.y], 1) - 1] = s.y;
        g_srclist[g_offset[d.z] + atomicSub(&g_count[d.z], 1) - 1] = s.z;
        g_srclist[g_offset[d.w] + atomicSub(&g_count[d.w], 1) - 1] = s.w;
    } else {
        for (; e < E; e++) {
            int dst = ei[E + e];
            g_srclist[g_offset[dst] + atomicSub(&g_count[dst], 1) - 1] = ei[e];
        }
    }
}

// ---------------------------------------------------------------------------
// Main: one warp per destination node. Lane l owns floats [4l, 4l+4) of the
// 128-float node vector; head h = l>>2 (4 lanes per 16-dim head).
// Software-pipelined x4: issue all 8 float4 gathers before consuming.

__device__ __forceinline__ void edge_accum(const float4& q4, const float4& k4,
                                           const float4& v4, float4& acc, float& z) {
    float d = q4.x * k4.x + q4.y * k4.y + q4.z * k4.z + q4.w * k4.w;
    d += __shfl_xor_sync(0xffffffffu, d, 1);
    d += __shfl_xor_sync(0xffffffffu, d, 2);
    d *= 0.25f;                                 // 1/sqrt(16)
    d = fminf(fmaxf(d, -5.f), 5.f);
    float s = __expf(d);
    z += s;
    acc.x += v4.x * s;
    acc.y += v4.y * s;
    acc.z += v4.z * s;
    acc.w += v4.w * s;
}

__global__ void __launch_bounds__(256)
attn_kernel(const float4* __restrict__ q,
            const float4* __restrict__ k,
            const float4* __restrict__ v,
            float4* __restrict__ out,
            int nnodes) {
    int gw   = (blockIdx.x * blockDim.x + threadIdx.x) >> 5;
    int lane = threadIdx.x & 31;
    if (gw >= nnodes) return;

    const int node = gw;
    const int beg = g_offset[node];
    const int end = g_offset[node + 1];

    const float4 q4 = q[node * 32 + lane];
    float4 acc = make_float4(0.f, 0.f, 0.f, 0.f);
    float  z   = 0.f;

    int i = beg;
    for (; i + 4 <= end; i += 4) {
        int s0 = __ldg(&g_srclist[i + 0]);
        int s1 = __ldg(&g_srclist[i + 1]);
        int s2 = __ldg(&g_srclist[i + 2]);
        int s3 = __ldg(&g_srclist[i + 3]);
        float4 k0 = __ldg(&k[s0 * 32 + lane]);
        float4 k1 = __ldg(&k[s1 * 32 + lane]);
        float4 k2 = __ldg(&k[s2 * 32 + lane]);
        float4 k3 = __ldg(&k[s3 * 32 + lane]);
        float4 v0 = __ldg(&v[s0 * 32 + lane]);
        float4 v1 = __ldg(&v[s1 * 32 + lane]);
        float4 v2 = __ldg(&v[s2 * 32 + lane]);
        float4 v3 = __ldg(&v[s3 * 32 + lane]);
        edge_accum(q4, k0, v0, acc, z);
        edge_accum(q4, k1, v1, acc, z);
        edge_accum(q4, k2, v2, acc, z);
        edge_accum(q4, k3, v3, acc, z);
    }
    for (; i < end; i++) {
        int src = __ldg(&g_srclist[i]);
        float4 k4 = __ldg(&k[src * 32 + lane]);
        float4 v4 = __ldg(&v[src * 32 + lane]);
        edge_accum(q4, k4, v4, acc, z);
    }

    float inv = 1.f / (z + 1e-6f);
    float4 o;
    o.x = acc.x * inv; o.y = acc.y * inv; o.z = acc.z * inv; o.w = acc.w * inv;
    out[node * 32 + lane] = o;
}

// ---------------------------------------------------------------------------
extern "C" void kernel_launch(void* const* d_in, const int* in_sizes, int n_in,
                              void* d_out, int out_size) {
    const float* q  = (const float*)d_in[0];
    const float* k  = (const float*)d_in[1];
    const float* v  = (const float*)d_in[2];
    const int*   ei = (const int*)d_in[3];

    int E      = in_sizes[3] / 2;
    int nnodes = in_sizes[0] / HD;

    void* count_ptr = nullptr;
    cudaGetSymbolAddress(&count_ptr, g_count);
    cudaMemsetAsync(count_ptr, 0, nnodes * sizeof(int));

    int eth = (E + 3) / 4;   // 4 edges per thread
    hist_kernel<<<(eth + 255) / 256, 256>>>(ei, E);
    scan_kernel<<<1, 1024>>>(nnodes);
    scatter_kernel<<<(eth + 255) / 256, 256>>>(ei, E);

    int threads = 256;                       // 8 warps/block -> 8 nodes/block
    int blocks  = (nnodes * 32 + threads - 1) / threads;
    attn_kernel<<<blocks, threads>>>((const float4*)q, (const float4*)k,
                                     (const float4*)v, (float4*)d_out, nnodes);
}

// round 4
// speedup vs baseline: 1.4889x; 1.4248x over previous
#include <cuda_runtime.h>

// Problem constants (fixed by reference): B=1, N=50000, H=8, D=16, E=800000
#define NNODES 50000
#define NEDGES 800000
#define HD     128          // H*D floats per node
#define SCAN_BS 256
#define SCAN_NBLK ((NNODES + SCAN_BS - 1) / SCAN_BS)   // 196

// Device-global scratch (no allocations allowed)
__device__ int g_count   [NNODES];        // histogram, then reused as scatter cursor
__device__ int g_offset  [NNODES + 1];
__device__ int g_srclist [NEDGES];
__device__ int g_blocksum[SCAN_NBLK];
__device__ int g_blockbase[SCAN_NBLK];

// ---------------------------------------------------------------------------
__global__ void hist_kernel(const int* __restrict__ ei, int E) {
    int t = blockIdx.x * blockDim.x + threadIdx.x;
    int e = t * 4;
    if (e + 4 <= E) {
        int4 d = *reinterpret_cast<const int4*>(&ei[E + e]);   // dst rows
        atomicAdd(&g_count[d.x], 1);
        atomicAdd(&g_count[d.y], 1);
        atomicAdd(&g_count[d.z], 1);
        atomicAdd(&g_count[d.w], 1);
    } else {
        for (; e < E; e++) atomicAdd(&g_count[ei[E + e]], 1);
    }
}

// ---------------------------------------------------------------------------
// Block-wide exclusive scan helper for 256 threads. Returns exclusive prefix;
// *total receives the block-wide sum (valid in all threads).
__device__ __forceinline__ int block_exscan_256(int val, int* total) {
    int lane = threadIdx.x & 31;
    int wid  = threadIdx.x >> 5;

    int inc = val;
    #pragma unroll
    for (int off = 1; off < 32; off <<= 1) {
        int t = __shfl_up_sync(0xffffffffu, inc, off);
        if (lane >= off) inc += t;
    }
    __shared__ int wsum[8];
    if (lane == 31) wsum[wid] = inc;
    __syncthreads();
    if (wid == 0) {
        int w = (lane < 8) ? wsum[lane] : 0;
        #pragma unroll
        for (int off = 1; off < 8; off <<= 1) {
            int t = __shfl_up_sync(0xffffffffu, w, off);
            if (lane >= off) w += t;
        }
        if (lane < 8) wsum[lane] = w;           // inclusive warp sums
    }
    __syncthreads();
    int warp_base = (wid == 0) ? 0 : wsum[wid - 1];
    *total = wsum[7];
    return warp_base + inc - val;               // exclusive prefix
}

// Phase 1: per-block exclusive scan of g_count -> g_offset (local), totals out.
__global__ void scan_local(int n) {
    int idx = blockIdx.x * SCAN_BS + threadIdx.x;
    int val = (idx < n) ? g_count[idx] : 0;
    int total;
    int ex = block_exscan_256(val, &total);
    if (idx < n) g_offset[idx] = ex;
    if (threadIdx.x == 0) g_blocksum[blockIdx.x] = total;
}

// Phase 2: single small block scans the block sums.
__global__ void scan_tops(int n) {
    int val = (threadIdx.x < SCAN_NBLK) ? g_blocksum[threadIdx.x] : 0;
    int total;
    int ex = block_exscan_256(val, &total);
    if (threadIdx.x < SCAN_NBLK) g_blockbase[threadIdx.x] = ex;
    if (threadIdx.x == 0) g_offset[n] = total;
}

// Phase 3: add block bases back.
__global__ void scan_add(int n) {
    int idx = blockIdx.x * SCAN_BS + threadIdx.x;
    if (idx < n) g_offset[idx] += g_blockbase[blockIdx.x];
}

// ---------------------------------------------------------------------------
// Scatter: reuse g_count as a downward cursor (rank order within a bucket is
// irrelevant — attention sum is order-independent).
__global__ void scatter_kernel(const int* __restrict__ ei, int E) {
    int t = blockIdx.x * blockDim.x + threadIdx.x;
    int e = t * 4;
    if (e + 4 <= E) {
        int4 s = *reinterpret_cast<const int4*>(&ei[e]);       // src rows
        int4 d = *reinterpret_cast<const int4*>(&ei[E + e]);   // dst rows
        g_srclist[g_offset[d.x] + atomicSub(&g_count[d.x], 1) - 1] = s.x;
        g_srclist[g_offset[d.y] + atomicSub(&g_count[d.y], 1) - 1] = s.y;
        g_srclist[g_offset[d.z] + atomicSub(&g_count[d.z], 1) - 1] = s.z;
        g_srclist[g_offset[d.w] + atomicSub(&g_count[d.w], 1) - 1] = s.w;
    } else {
        for (; e < E; e++) {
            int dst = ei[E + e];
            g_srclist[g_offset[dst] + atomicSub(&g_count[dst], 1) - 1] = ei[e];
        }
    }
}

// ---------------------------------------------------------------------------
// Main: one warp per destination node. Lane l owns floats [4l, 4l+4) of the
// 128-float node vector; head h = l>>2 (4 lanes per 16-dim head).
// Software-pipelined x4: issue all 8 float4 gathers before consuming.

__device__ __forceinline__ void edge_accum(const float4& q4, const float4& k4,
                                           const float4& v4, float4& acc, float& z) {
    float d = q4.x * k4.x + q4.y * k4.y + q4.z * k4.z + q4.w * k4.w;
    d += __shfl_xor_sync(0xffffffffu, d, 1);
    d += __shfl_xor_sync(0xffffffffu, d, 2);
    d *= 0.25f;                                 // 1/sqrt(16)
    d = fminf(fmaxf(d, -5.f), 5.f);
    float s = __expf(d);
    z += s;
    acc.x += v4.x * s;
    acc.y += v4.y * s;
    acc.z += v4.z * s;
    acc.w += v4.w * s;
}

__global__ void __launch_bounds__(256)
attn_kernel(const float4* __restrict__ q,
            const float4* __restrict__ k,
            const float4* __restrict__ v,
            float4* __restrict__ out,
            int nnodes) {
    int gw   = (blockIdx.x * blockDim.x + threadIdx.x) >> 5;
    int lane = threadIdx.x & 31;
    if (gw >= nnodes) return;

    const int node = gw;
    const int beg = g_offset[node];
    const int end = g_offset[node + 1];

    const float4 q4 = q[node * 32 + lane];
    float4 acc = make_float4(0.f, 0.f, 0.f, 0.f);
    float  z   = 0.f;

    int i = beg;
    for (; i + 4 <= end; i += 4) {
        int s0 = __ldg(&g_srclist[i + 0]);
        int s1 = __ldg(&g_srclist[i + 1]);
        int s2 = __ldg(&g_srclist[i + 2]);
        int s3 = __ldg(&g_srclist[i + 3]);
        float4 k0 = __ldg(&k[s0 * 32 + lane]);
        float4 k1 = __ldg(&k[s1 * 32 + lane]);
        float4 k2 = __ldg(&k[s2 * 32 + lane]);
        float4 k3 = __ldg(&k[s3 * 32 + lane]);
        float4 v0 = __ldg(&v[s0 * 32 + lane]);
        float4 v1 = __ldg(&v[s1 * 32 + lane]);
        float4 v2 = __ldg(&v[s2 * 32 + lane]);
        float4 v3 = __ldg(&v[s3 * 32 + lane]);
        edge_accum(q4, k0, v0, acc, z);
        edge_accum(q4, k1, v1, acc, z);
        edge_accum(q4, k2, v2, acc, z);
        edge_accum(q4, k3, v3, acc, z);
    }
    for (; i < end; i++) {
        int src = __ldg(&g_srclist[i]);
        float4 k4 = __ldg(&k[src * 32 + lane]);
        float4 v4 = __ldg(&v[src * 32 + lane]);
        edge_accum(q4, k4, v4, acc, z);
    }

    float inv = 1.f / (z + 1e-6f);
    float4 o;
    o.x = acc.x * inv; o.y = acc.y * inv; o.z = acc.z * inv; o.w = acc.w * inv;
    out[node * 32 + lane] = o;
}

// ---------------------------------------------------------------------------
extern "C" void kernel_launch(void* const* d_in, const int* in_sizes, int n_in,
                              void* d_out, int out_size) {
    const float* q  = (const float*)d_in[0];
    const float* k  = (const float*)d_in[1];
    const float* v  = (const float*)d_in[2];
    const int*   ei = (const int*)d_in[3];

    int E      = in_sizes[3] / 2;
    int nnodes = in_sizes[0] / HD;

    void* count_ptr = nullptr;
    cudaGetSymbolAddress(&count_ptr, g_count);
    cudaMemsetAsync(count_ptr, 0, nnodes * sizeof(int));

    int eth = (E + 3) / 4;   // 4 edges per thread
    hist_kernel<<<(eth + 255) / 256, 256>>>(ei, E);

    int nblk = (nnodes + SCAN_BS - 1) / SCAN_BS;
    scan_local<<<nblk, SCAN_BS>>>(nnodes);
    scan_tops<<<1, SCAN_BS>>>(nnodes);
    scan_add<<<nblk, SCAN_BS>>>(nnodes);

    scatter_kernel<<<(eth + 255) / 256, 256>>>(ei, E);

    int threads = 256;                       // 8 warps/block -> 8 nodes/block
    int blocks  = (nnodes * 32 + threads - 1) / threads;
    attn_kernel<<<blocks, threads>>>((const float4*)q, (const float4*)k,
                                     (const float4*)v, (float4*)d_out, nnodes);
}